// round 15
// baseline (speedup 1.0000x reference)
#include <cuda_runtime.h>
#include <cuda_bf16.h>
#include <cstdint>
#include <cstddef>

#define DEPN  96
#define HEADN 96
#define BSZN  16
#define DIMN  512
#define RELN  128

// bf16 scratch
__device__ __align__(16) uint8_t g_Inb[2 * 1536 * DIMN * 2];   // outs rows 0..1535, gs rows 1536..
__device__ __align__(16) uint8_t g_Wtb[2 * DIMN * DIMN * 2];   // [which][e][k]
// Wp permuted: row n, 32B blocks, word w -> slot 2*(w&3)+(w>>2). +128B overfetch pad.
__device__ __align__(16) uint8_t g_Wpp[RELN * DIMN * 2 + 128];
// P/Q stored with the same per-32B-block word permutation
__device__ __align__(16) uint8_t g_Pb[DEPN * BSZN * DIMN * 2]; // bf16(outs@Wt1 + bt)
__device__ __align__(16) uint8_t g_Qb[HEADN * BSZN * DIMN * 2];

// pack two floats -> bf16x2 (lo = first arg)
__device__ __forceinline__ uint32_t f2bf2(float lo, float hi) {
    uint32_t r;
    asm("cvt.rn.bf16x2.f32 %0, %1, %2;" : "=r"(r) : "f"(hi), "f"(lo));
    return r;
}

// relu(p + q) on bf16x2 pairs
__device__ __forceinline__ uint32_t bf2_addrelu(uint32_t p, uint32_t q) {
    uint32_t s, r;
    asm("add.rn.bf16x2 %0, %1, %2;" : "=r"(s) : "r"(p), "r"(q));
    asm("max.bf16x2 %0, %1, %2;" : "=r"(r) : "r"(s), "r"(0u));
    return r;
}

__device__ __forceinline__ uint32_t smem_u32(const void* p) {
    uint32_t a;
    asm("{ .reg .u64 t; cvta.to.shared.u64 t, %1; cvt.u32.u64 %0, t; }"
        : "=r"(a) : "l"(p));
    return a;
}

__device__ __forceinline__ void cp16(uint32_t dst, const void* src) {
    asm volatile("cp.async.cg.shared.global [%0], [%1], 16;"
        :: "r"(dst), "l"(src));
}
#define CP_COMMIT() asm volatile("cp.async.commit_group;" ::: "memory")
#define CP_WAIT0()  asm volatile("cp.async.wait_group 0;" ::: "memory")

__device__ __forceinline__ uint2 lds64(uint32_t addr) {
    uint2 v;
    asm volatile("ld.shared.v2.b32 {%0,%1}, [%2];" : "=r"(v.x), "=r"(v.y) : "r"(addr));
    return v;
}

__device__ __forceinline__ void ldsm_x4(uint32_t* r, uint32_t addr) {
    asm volatile("ldmatrix.sync.aligned.m8n8.x4.shared.b16 {%0,%1,%2,%3}, [%4];"
        : "=r"(r[0]), "=r"(r[1]), "=r"(r[2]), "=r"(r[3]) : "r"(addr));
}

__device__ __forceinline__ void mma_bf16(float* c, const uint32_t* a, const uint32_t* b) {
    asm volatile(
        "mma.sync.aligned.m16n8k16.row.col.f32.bf16.bf16.f32 "
        "{%0,%1,%2,%3}, {%4,%5,%6,%7}, {%8,%9}, {%0,%1,%2,%3};\n"
        : "+f"(c[0]), "+f"(c[1]), "+f"(c[2]), "+f"(c[3])
        : "r"(a[0]), "r"(a[1]), "r"(a[2]), "r"(a[3]), "r"(b[0]), "r"(b[1]));
}

#define ASTRIDE 144    // smem row pad for ldmatrix kernels (projb only)

// ---------------------------------------------------------------------------
// Kernel 0: fp32 -> bf16 conversion: outs, gs, Wt (reordered), Wp (permuted).
// ---------------------------------------------------------------------------
#define R_OUTS 196608                 // 1536*512/4
#define R_GS   (R_OUTS + 196608)
#define R_WT   (R_GS + 131072)        // 2*512*512/4
#define R_WP   (R_WT + 16384)         // 128*512/4

__global__ void prep_kernel(const float* __restrict__ outs,
                            const float* __restrict__ gs,
                            const float* __restrict__ Wt,
                            const float* __restrict__ Wp)
{
    int o = blockIdx.x * 256 + threadIdx.x;
    if (o >= R_WT) {
        // Wp: write the two output words to their permuted slots
        int i = o - R_WT;                 // float4 index over [128][512]
        float4 v = reinterpret_cast<const float4*>(Wp)[i];
        int row = i >> 7, c4 = i & 127;
        int w0 = 2 * c4;                  // word index within row (256 words)
        int blk = w0 >> 3;
        int win0 = w0 & 7, win1 = win0 + 1;
        int s0 = 2 * (win0 & 3) + (win0 >> 2);
        int s1 = 2 * (win1 & 3) + (win1 >> 2);
        uint8_t* base = g_Wpp + (size_t)row * 1024 + (size_t)blk * 32;
        *reinterpret_cast<uint32_t*>(base + s0 * 4) = f2bf2(v.x, v.y);
        *reinterpret_cast<uint32_t*>(base + s1 * 4) = f2bf2(v.z, v.w);
        return;
    }
    float4 v;
    uint8_t* dst;
    if (o < R_OUTS) {
        v = reinterpret_cast<const float4*>(outs)[o];
        dst = g_Inb + (size_t)o * 8;
    } else if (o < R_GS) {
        int i = o - R_OUTS;
        v = reinterpret_cast<const float4*>(gs)[i];
        dst = g_Inb + (size_t)(R_OUTS + i) * 8;
    } else {
        int d = o - R_GS;                 // [which][e][k4]
        int which = d >> 16;
        int r = d & 65535;
        int e = r >> 7, k4 = r & 127;
        v = reinterpret_cast<const float4*>(Wt)[e * 256 + which * 128 + k4];
        dst = g_Wtb + (size_t)d * 8;
    }
    uint2 u;
    u.x = f2bf2(v.x, v.y);
    u.y = f2bf2(v.z, v.w);
    *reinterpret_cast<uint2*>(dst) = u;
}

// ---------------------------------------------------------------------------
// Kernel 1: projections, pure bf16 GEMM; outputs written word-permuted.
// ---------------------------------------------------------------------------
#define PJ_A(s) ((s) * 18432)
#define PJ_B(s) (36864 + (s) * 18432)
#define PJ_SMEM 73728

__global__ __launch_bounds__(256, 2)
void projb_kernel(const float* __restrict__ bt)
{
    extern __shared__ __align__(16) char dsm[];
    const uint32_t smb = smem_u32(dsm);

    const int which = blockIdx.z;
    const int m0 = blockIdx.y * 128;
    const int e0 = blockIdx.x * 128;
    const uint8_t* Arows = g_Inb + (size_t)which * 1536 * (DIMN * 2);
    const uint8_t* Brows = g_Wtb + (size_t)which * DIMN * (DIMN * 2);

    const int tid = threadIdx.x;
    const int wid = tid >> 5;
    const int lane = tid & 31;
    const int wm = wid >> 2;
    const int wn = wid & 3;
    const int g = lane >> 2;
    const int tg = lane & 3;

    float c[4][4][4];
    #pragma unroll
    for (int i = 0; i < 4; i++)
        #pragma unroll
        for (int j = 0; j < 4; j++)
            #pragma unroll
            for (int k = 0; k < 4; k++) c[i][j][k] = 0.f;

    const uint32_t aRowOff = (uint32_t)(lane & 15) * ASTRIDE + (uint32_t)(lane >> 4) * 16;
    const uint32_t bRow = (uint32_t)(wn * 32 + ((lane >> 4) << 3) + (lane & 7));
    const uint32_t bOff = bRow * ASTRIDE + (uint32_t)((lane >> 3) & 1) * 16;

    auto issue = [&](int j, int s) {
        #pragma unroll
        for (int i = 0; i < 4; i++) {
            int o = i * 256 + tid;
            int n = o >> 3, ch = o & 7;
            cp16(smb + PJ_A(s) + (uint32_t)n * ASTRIDE + (uint32_t)ch * 16,
                 Arows + (size_t)(m0 + n) * (DIMN * 2) + (size_t)j * 128 + (size_t)ch * 16);
            cp16(smb + PJ_B(s) + (uint32_t)n * ASTRIDE + (uint32_t)ch * 16,
                 Brows + (size_t)(e0 + n) * (DIMN * 2) + (size_t)j * 128 + (size_t)ch * 16);
        }
        CP_COMMIT();
    };

    issue(0, 0);
    #pragma unroll 1
    for (int j = 0; j < 8; j++) {
        const int cur = j & 1;
        CP_WAIT0();
        __syncthreads();
        if (j < 7) issue(j + 1, cur ^ 1);

        const uint32_t AsB = smb + PJ_A(cur);
        const uint32_t BsB = smb + PJ_B(cur);
        #pragma unroll
        for (int ks = 0; ks < 4; ks++) {
            uint32_t a[4][4];
            #pragma unroll
            for (int mf = 0; mf < 4; mf++)
                ldsm_x4(a[mf], AsB + (uint32_t)(wm * 64 + mf * 16) * ASTRIDE
                                     + aRowOff + ks * 32);
            uint32_t bb[8];
            ldsm_x4(&bb[0], BsB + bOff + ks * 32);
            ldsm_x4(&bb[4], BsB + 16 * ASTRIDE + bOff + ks * 32);
            #pragma unroll
            for (int nf = 0; nf < 4; nf++)
                #pragma unroll
                for (int mf = 0; mf < 4; mf++)
                    mma_bf16(c[mf][nf], a[mf], &bb[nf * 2]);
        }
    }

    uint8_t* Outb = which ? g_Qb : g_Pb;
    #pragma unroll
    for (int mf = 0; mf < 4; mf++) {
        #pragma unroll
        for (int nf = 0; nf < 4; nf++) {
            int r = m0 + wm * 64 + mf * 16 + g;
            int col = e0 + wn * 32 + nf * 8 + 2 * tg;   // even
            float b0 = 0.f, b1 = 0.f;
            if (!which) { b0 = bt[col]; b1 = bt[col + 1]; }
            uint32_t pbyte = (uint32_t)(col >> 4) * 32 + (uint32_t)(2 * tg + (nf & 1)) * 4;
            *reinterpret_cast<uint32_t*>(Outb + (size_t)r * (DIMN * 2) + pbyte) =
                f2bf2(c[mf][nf][0] + b0, c[mf][nf][1] + b1);
            *reinterpret_cast<uint32_t*>(Outb + (size_t)(r + 8) * (DIMN * 2) + pbyte) =
                f2bf2(c[mf][nf][2] + b0, c[mf][nf][3] + b1);
        }
    }
}

// ---------------------------------------------------------------------------
// Kernel 2: fused pairwise scores + log-softmax — BARRIER-FREE mainloop.
// P/Q staged once in smem (permuted); A fragments via broadcast LDS.64;
// B fragments via LDG.64 straight from permuted global Wp (L2/L1-hot),
// prefetched one step ahead. One flat loop over 32 k-steps, no syncs.
// ---------------------------------------------------------------------------
#define QSTRIDE 1056
#define OFF_BPS 0
#define OFF_PB  1024                        // 16 x 1024 = 16384
#define OFF_QB  (OFF_PB + 16384)            // 8 x 1056 = 8448 -> ends 25856
#define REL_SMEM 68608                      // epilogue Ssm: 1024 + 128*132*4

__global__ __launch_bounds__(256, 2)
void rel_kernel(const float* __restrict__ bp,
                float* __restrict__ out)
{
    extern __shared__ __align__(16) char dsm[];
    const uint32_t smb = smem_u32(dsm);
    float* bps = reinterpret_cast<float*>(dsm + OFF_BPS);

    const int hblk = blockIdx.x;  // 0..11
    const int dblk = blockIdx.y;  // 0..5
    const int b = blockIdx.z;     // 0..15

    const int tid = threadIdx.x;
    const int wid = tid >> 5;
    const int lane = tid & 31;
    const int wm = wid >> 2;
    const int wn = wid & 3;
    const int g = lane >> 2;
    const int tg = lane & 3;

    if (tid < RELN) bps[tid] = bp[tid];

    float c[4][4][4];
    #pragma unroll
    for (int i = 0; i < 4; i++)
        #pragma unroll
        for (int j = 0; j < 4; j++)
            #pragma unroll
            for (int k = 0; k < 4; k++) c[i][j][k] = 0.f;

    // thread-constant operand base addresses
    const uint32_t qb2 = smb + OFF_QB + (uint32_t)g * QSTRIDE + (uint32_t)tg * 8;
    const uint32_t pb2 = smb + OFF_PB + (uint32_t)(wm * 8) * 1024 + (uint32_t)tg * 8;
    const uint8_t* bwp = g_Wpp + (size_t)(wn * 32 + g) * 1024 + (size_t)tg * 8;

    // prologue: stage P (stride 1024) and Q (stride 1056)
    {
        #pragma unroll
        for (int i = 0; i < 4; i++) {
            int o = i * 256 + tid;
            int row = o >> 6, ch = o & 63;
            cp16(smb + OFF_PB + (uint32_t)row * 1024 + (uint32_t)ch * 16,
                 g_Pb + ((size_t)(dblk * 16 + row) * BSZN + b) * 1024 + (size_t)ch * 16);
        }
        #pragma unroll
        for (int i = 0; i < 2; i++) {
            int o = i * 256 + tid;
            int row = o >> 6, ch = o & 63;
            cp16(smb + OFF_QB + (uint32_t)row * QSTRIDE + (uint32_t)ch * 16,
                 g_Qb + ((size_t)(hblk * 8 + row) * BSZN + b) * 1024 + (size_t)ch * 16);
        }
        CP_COMMIT();
        CP_WAIT0();
        __syncthreads();
    }

    // B fragment loader: 4 LDG.64 from permuted global Wp
    uint32_t bb[2][8];
    auto loadB = [&](uint32_t* dst, int s) {
        #pragma unroll
        for (int nf = 0; nf < 4; nf++) {
            uint2 v = *reinterpret_cast<const uint2*>(bwp + (size_t)nf * 8192 + (size_t)s * 32);
            dst[nf * 2] = v.x;
            dst[nf * 2 + 1] = v.y;
        }
    };

    // flat barrier-free mainloop over 32 k16-steps
    loadB(bb[0], 0);
    #pragma unroll 4
    for (int s = 0; s < 32; s++) {
        const int cu = s & 1, nx = cu ^ 1;
        loadB(bb[nx], s + 1);              // s=31 overfetch lands in pad
        const uint32_t ko = (uint32_t)s * 32;
        uint2 q = lds64(qb2 + ko);
        uint2 p[4][2];
        #pragma unroll
        for (int mf = 0; mf < 4; mf++) {
            const uint32_t pbase = pb2 + (uint32_t)mf * 2048 + ko;
            p[mf][0] = lds64(pbase);
            p[mf][1] = lds64(pbase + 1024);
        }
        #pragma unroll
        for (int mf = 0; mf < 4; mf++) {
            uint32_t a[4];
            a[0] = bf2_addrelu(p[mf][0].x, q.x);
            a[1] = bf2_addrelu(p[mf][1].x, q.x);
            a[2] = bf2_addrelu(p[mf][0].y, q.y);
            a[3] = bf2_addrelu(p[mf][1].y, q.y);
            #pragma unroll
            for (int nf = 0; nf < 4; nf++)
                mma_bf16(c[mf][nf], a, &bb[cu][nf * 2]);
        }
    }

    // single-pass epilogue: stage 128x132, per-row log-softmax
    float* Ssm = reinterpret_cast<float*>(dsm + 1024);
    __syncthreads();   // all warps done reading P/Q before overwrite
    #pragma unroll
    for (int mf = 0; mf < 4; mf++) {
        #pragma unroll
        for (int nf = 0; nf < 4; nf++) {
            int rl = wm * 64 + mf * 16 + g;
            int col = wn * 32 + nf * 8 + 2 * tg;
            *reinterpret_cast<float2*>(&Ssm[rl * 132 + col]) =
                make_float2(c[mf][nf][0], c[mf][nf][1]);
            *reinterpret_cast<float2*>(&Ssm[(rl + 8) * 132 + col]) =
                make_float2(c[mf][nf][2], c[mf][nf][3]);
        }
    }
    __syncthreads();
    #pragma unroll
    for (int i = 0; i < 16; i++) {
        int rl = wid * 16 + i;
        float4 v = *reinterpret_cast<const float4*>(&Ssm[rl * 132 + lane * 4]);
        v.x += bps[lane * 4 + 0];
        v.y += bps[lane * 4 + 1];
        v.z += bps[lane * 4 + 2];
        v.w += bps[lane * 4 + 3];
        float mx = fmaxf(fmaxf(v.x, v.y), fmaxf(v.z, v.w));
        #pragma unroll
        for (int off = 16; off > 0; off >>= 1)
            mx = fmaxf(mx, __shfl_xor_sync(0xffffffffu, mx, off));
        mx = fmaxf(mx, 0.f);  // nil column
        float se = __expf(v.x - mx) + __expf(v.y - mx) +
                   __expf(v.z - mx) + __expf(v.w - mx);
        #pragma unroll
        for (int off = 16; off > 0; off >>= 1)
            se += __shfl_xor_sync(0xffffffffu, se, off);
        se += __expf(-mx);  // nil column contribution
        float lse = mx + __logf(se);
        int d = dblk * 16 + (rl >> 3);
        int h = hblk * 8 + (rl & 7);
        float* op = out + (size_t)((d * BSZN + b) * HEADN + h) * (RELN + 1);
        if (lane == 0) op[0] = -lse;
        op[1 + lane * 4 + 0] = v.x - lse;
        op[1 + lane * 4 + 1] = v.y - lse;
        op[1 + lane * 4 + 2] = v.z - lse;
        op[1 + lane * 4 + 3] = v.w - lse;
    }
}

// ---------------------------------------------------------------------------
extern "C" void kernel_launch(void* const* d_in, const int* in_sizes, int n_in,
                              void* d_out, int out_size) {
    const float* outs = (const float*)d_in[0];  // [96,16,512]
    const float* gs   = (const float*)d_in[1];  // [96,16,512]
    const float* Wt   = (const float*)d_in[2];  // [512,1024]
    const float* bt   = (const float*)d_in[3];  // [512]
    const float* Wp   = (const float*)d_in[4];  // [128,512]
    const float* bp   = (const float*)d_in[5];  // [128]
    float* out = (float*)d_out;                 // [96,16,96,129]

    (void)in_sizes; (void)n_in; (void)out_size;

    static bool attr_set = false;
    if (!attr_set) {
        cudaFuncSetAttribute(rel_kernel,
                             cudaFuncAttributeMaxDynamicSharedMemorySize,
                             REL_SMEM);
        cudaFuncSetAttribute(projb_kernel,
                             cudaFuncAttributeMaxDynamicSharedMemorySize,
                             PJ_SMEM);
        attr_set = true;
    }

    prep_kernel<<<R_WP / 256, 256>>>(outs, gs, Wt, Wp);        // 2112 blocks

    dim3 pg(DIMN / 128, 1536 / 128, 2);           // (4, 12, 2)
    projb_kernel<<<pg, 256, PJ_SMEM>>>(bt);

    dim3 mg(HEADN / 8, DEPN / 16, BSZN);          // (12, 6, 16)
    rel_kernel<<<mg, 256, REL_SMEM>>>(bp, out);
}

// round 16
// speedup vs baseline: 1.0683x; 1.0683x over previous
#include <cuda_runtime.h>
#include <cuda_bf16.h>
#include <cstdint>
#include <cstddef>

#define DEPN  96
#define HEADN 96
#define BSZN  16
#define DIMN  512
#define RELN  128

// bf16 scratch
__device__ __align__(16) uint8_t g_Inb[2 * 1536 * DIMN * 2];   // outs rows 0..1535, gs rows 1536..
__device__ __align__(16) uint8_t g_Wtb[2 * DIMN * DIMN * 2];   // [which][e][k]
__device__ __align__(16) uint8_t g_Wpb[RELN * DIMN * 2];
// P/Q stored with per-32B-block word permutation perm(w)=2*(w&3)+(w>>2)
__device__ __align__(16) uint8_t g_Pb[DEPN * BSZN * DIMN * 2]; // bf16(outs@Wt1 + bt)
__device__ __align__(16) uint8_t g_Qb[HEADN * BSZN * DIMN * 2];

// pack two floats -> bf16x2 (lo = first arg)
__device__ __forceinline__ uint32_t f2bf2(float lo, float hi) {
    uint32_t r;
    asm("cvt.rn.bf16x2.f32 %0, %1, %2;" : "=r"(r) : "f"(hi), "f"(lo));
    return r;
}

// relu(p + q) on bf16x2 pairs
__device__ __forceinline__ uint32_t bf2_addrelu(uint32_t p, uint32_t q) {
    uint32_t s, r;
    asm("add.rn.bf16x2 %0, %1, %2;" : "=r"(s) : "r"(p), "r"(q));
    asm("max.bf16x2 %0, %1, %2;" : "=r"(r) : "r"(s), "r"(0u));
    return r;
}

__device__ __forceinline__ uint32_t smem_u32(const void* p) {
    uint32_t a;
    asm("{ .reg .u64 t; cvta.to.shared.u64 t, %1; cvt.u32.u64 %0, t; }"
        : "=r"(a) : "l"(p));
    return a;
}

__device__ __forceinline__ void cp16(uint32_t dst, const void* src) {
    asm volatile("cp.async.cg.shared.global [%0], [%1], 16;"
        :: "r"(dst), "l"(src));
}
#define CP_COMMIT() asm volatile("cp.async.commit_group;" ::: "memory")
#define CP_WAIT0()  asm volatile("cp.async.wait_group 0;" ::: "memory")

template<int N> __device__ __forceinline__ void cp_wait() {
    asm volatile("cp.async.wait_group %0;" :: "n"(N) : "memory");
}

__device__ __forceinline__ uint2 lds64(uint32_t addr) {
    uint2 v;
    asm volatile("ld.shared.v2.b32 {%0,%1}, [%2];" : "=r"(v.x), "=r"(v.y) : "r"(addr));
    return v;
}

__device__ __forceinline__ void ldsm_x4(uint32_t* r, uint32_t addr) {
    asm volatile("ldmatrix.sync.aligned.m8n8.x4.shared.b16 {%0,%1,%2,%3}, [%4];"
        : "=r"(r[0]), "=r"(r[1]), "=r"(r[2]), "=r"(r[3]) : "r"(addr));
}

__device__ __forceinline__ void mma_bf16(float* c, const uint32_t* a, const uint32_t* b) {
    asm volatile(
        "mma.sync.aligned.m16n8k16.row.col.f32.bf16.bf16.f32 "
        "{%0,%1,%2,%3}, {%4,%5,%6,%7}, {%8,%9}, {%0,%1,%2,%3};\n"
        : "+f"(c[0]), "+f"(c[1]), "+f"(c[2]), "+f"(c[3])
        : "r"(a[0]), "r"(a[1]), "r"(a[2]), "r"(a[3]), "r"(b[0]), "r"(b[1]));
}

#define ASTRIDE 144    // 128B data + 16B pad per smem row (conflict-free ldmatrix)

// ---------------------------------------------------------------------------
// Kernel 0: fp32 -> bf16 conversion for outs, gs, Wt (reordered), Wp.
// ---------------------------------------------------------------------------
#define R_OUTS 196608                 // 1536*512/4
#define R_GS   (R_OUTS + 196608)
#define R_WT   (R_GS + 131072)        // 2*512*512/4
#define R_WP   (R_WT + 16384)         // 128*512/4

__global__ void prep_kernel(const float* __restrict__ outs,
                            const float* __restrict__ gs,
                            const float* __restrict__ Wt,
                            const float* __restrict__ Wp)
{
    int o = blockIdx.x * 256 + threadIdx.x;
    float4 v;
    uint8_t* dst;
    if (o < R_OUTS) {
        v = reinterpret_cast<const float4*>(outs)[o];
        dst = g_Inb + (size_t)o * 8;
    } else if (o < R_GS) {
        int i = o - R_OUTS;
        v = reinterpret_cast<const float4*>(gs)[i];
        dst = g_Inb + (size_t)(R_OUTS + i) * 8;
    } else if (o < R_WT) {
        int d = o - R_GS;                 // [which][e][k4]
        int which = d >> 16;
        int r = d & 65535;
        int e = r >> 7, k4 = r & 127;
        v = reinterpret_cast<const float4*>(Wt)[e * 256 + which * 128 + k4];
        dst = g_Wtb + (size_t)d * 8;
    } else {
        int i = o - R_WT;
        v = reinterpret_cast<const float4*>(Wp)[i];
        dst = g_Wpb + (size_t)i * 8;
    }
    uint2 u;
    u.x = f2bf2(v.x, v.y);
    u.y = f2bf2(v.z, v.w);
    *reinterpret_cast<uint2*>(dst) = u;
}

// ---------------------------------------------------------------------------
// Kernel 1: projections, pure bf16 GEMM. Output rows written in the
// fragment-permuted word order: word w of each 32B block -> 2*(w&3)+(w>>2).
// ---------------------------------------------------------------------------
#define PJ_A(s) ((s) * 18432)
#define PJ_B(s) (36864 + (s) * 18432)
#define PJ_SMEM 73728

__global__ __launch_bounds__(256, 2)
void projb_kernel(const float* __restrict__ bt)
{
    extern __shared__ __align__(16) char dsm[];
    const uint32_t smb = smem_u32(dsm);

    const int which = blockIdx.z;
    const int m0 = blockIdx.y * 128;
    const int e0 = blockIdx.x * 128;
    const uint8_t* Arows = g_Inb + (size_t)which * 1536 * (DIMN * 2);
    const uint8_t* Brows = g_Wtb + (size_t)which * DIMN * (DIMN * 2);

    const int tid = threadIdx.x;
    const int wid = tid >> 5;
    const int lane = tid & 31;
    const int wm = wid >> 2;
    const int wn = wid & 3;
    const int g = lane >> 2;
    const int tg = lane & 3;

    float c[4][4][4];
    #pragma unroll
    for (int i = 0; i < 4; i++)
        #pragma unroll
        for (int j = 0; j < 4; j++)
            #pragma unroll
            for (int k = 0; k < 4; k++) c[i][j][k] = 0.f;

    const uint32_t aRowOff = (uint32_t)(lane & 15) * ASTRIDE + (uint32_t)(lane >> 4) * 16;
    const uint32_t bRow = (uint32_t)(wn * 32 + ((lane >> 4) << 3) + (lane & 7));
    const uint32_t bOff = bRow * ASTRIDE + (uint32_t)((lane >> 3) & 1) * 16;

    auto issue = [&](int j, int s) {
        #pragma unroll
        for (int i = 0; i < 4; i++) {
            int o = i * 256 + tid;
            int n = o >> 3, ch = o & 7;
            cp16(smb + PJ_A(s) + (uint32_t)n * ASTRIDE + (uint32_t)ch * 16,
                 Arows + (size_t)(m0 + n) * (DIMN * 2) + (size_t)j * 128 + (size_t)ch * 16);
            cp16(smb + PJ_B(s) + (uint32_t)n * ASTRIDE + (uint32_t)ch * 16,
                 Brows + (size_t)(e0 + n) * (DIMN * 2) + (size_t)j * 128 + (size_t)ch * 16);
        }
        CP_COMMIT();
    };

    issue(0, 0);
    #pragma unroll 1
    for (int j = 0; j < 8; j++) {
        const int cur = j & 1;
        CP_WAIT0();
        __syncthreads();
        if (j < 7) issue(j + 1, cur ^ 1);

        const uint32_t AsB = smb + PJ_A(cur);
        const uint32_t BsB = smb + PJ_B(cur);
        #pragma unroll
        for (int ks = 0; ks < 4; ks++) {
            uint32_t a[4][4];
            #pragma unroll
            for (int mf = 0; mf < 4; mf++)
                ldsm_x4(a[mf], AsB + (uint32_t)(wm * 64 + mf * 16) * ASTRIDE
                                     + aRowOff + ks * 32);
            uint32_t bb[8];
            ldsm_x4(&bb[0], BsB + bOff + ks * 32);
            ldsm_x4(&bb[4], BsB + 16 * ASTRIDE + bOff + ks * 32);
            #pragma unroll
            for (int nf = 0; nf < 4; nf++)
                #pragma unroll
                for (int mf = 0; mf < 4; mf++)
                    mma_bf16(c[mf][nf], a[mf], &bb[nf * 2]);
        }
    }

    uint8_t* Outb = which ? g_Qb : g_Pb;
    #pragma unroll
    for (int mf = 0; mf < 4; mf++) {
        #pragma unroll
        for (int nf = 0; nf < 4; nf++) {
            int r = m0 + wm * 64 + mf * 16 + g;
            int col = e0 + wn * 32 + nf * 8 + 2 * tg;   // even
            float b0 = 0.f, b1 = 0.f;
            if (!which) { b0 = bt[col]; b1 = bt[col + 1]; }
            // permuted store: block (col>>4)*32B, word slot 2tg + (nf&1)
            uint32_t pbyte = (uint32_t)(col >> 4) * 32 + (uint32_t)(2 * tg + (nf & 1)) * 4;
            *reinterpret_cast<uint32_t*>(Outb + (size_t)r * (DIMN * 2) + pbyte) =
                f2bf2(c[mf][nf][0] + b0, c[mf][nf][1] + b1);
            *reinterpret_cast<uint32_t*>(Outb + (size_t)(r + 8) * (DIMN * 2) + pbyte) =
                f2bf2(c[mf][nf][2] + b0, c[mf][nf][3] + b1);
        }
    }
}

// ---------------------------------------------------------------------------
// Kernel 2: fused pairwise scores + log-softmax. Register-direct A fragments
// (permuted P/Q, LDS.64), B in SMEM via cp.async with a FOUR-stage ring and
// 3-chunk prefetch distance: the wait at chunk j is for data issued 3 chunks
// earlier -> staging latency never exposed. Wait precedes the barrier
// (wait-then-sync gives cross-thread visibility).
// ---------------------------------------------------------------------------
#define QSTRIDE 1056
#define OFF_BPS 0
#define OFF_PB  1024                        // 16 x 1024 = 16384
#define OFF_QB  (OFF_PB + 16384)            // 8 x 1056 = 8448 -> ends 25856
#define OFF_B(s) (25856 + (s) * (128 * ASTRIDE))
#define REL_SMEM (25856 + 4 * (128 * ASTRIDE))   // 99584

__global__ __launch_bounds__(256, 2)
void rel_kernel(const float* __restrict__ bp,
                float* __restrict__ out)
{
    extern __shared__ __align__(16) char dsm[];
    const uint32_t smb = smem_u32(dsm);
    float* bps = reinterpret_cast<float*>(dsm + OFF_BPS);

    const int hblk = blockIdx.x;  // 0..11
    const int dblk = blockIdx.y;  // 0..5
    const int b = blockIdx.z;     // 0..15

    const int tid = threadIdx.x;
    const int wid = tid >> 5;
    const int lane = tid & 31;
    const int wm = wid >> 2;
    const int wn = wid & 3;
    const int g = lane >> 2;
    const int tg = lane & 3;

    if (tid < RELN) bps[tid] = bp[tid];

    float c[4][4][4];
    #pragma unroll
    for (int i = 0; i < 4; i++)
        #pragma unroll
        for (int j = 0; j < 4; j++)
            #pragma unroll
            for (int k = 0; k < 4; k++) c[i][j][k] = 0.f;

    // per-thread constant addresses (permuted layout: pair at tg*8)
    const uint32_t qb2 = smb + OFF_QB + (uint32_t)g * QSTRIDE + (uint32_t)tg * 8;
    const uint32_t pb2 = smb + OFF_PB + (uint32_t)(wm * 8) * 1024 + (uint32_t)tg * 8;

    const uint32_t bRow = (uint32_t)(wn * 32 + ((lane >> 4) << 3) + (lane & 7));
    const uint32_t bOff = bRow * ASTRIDE + (uint32_t)((lane >> 3) & 1) * 16;

    auto issue_B = [&](int j, int s) {
        const uint32_t stb = smb + OFF_B(s);
        #pragma unroll
        for (int i = 0; i < 4; i++) {
            int o = i * 256 + tid;
            int n = o >> 3, ch = o & 7;
            cp16(stb + (uint32_t)n * ASTRIDE + (uint32_t)ch * 16,
                 g_Wpb + (size_t)n * (DIMN * 2) + (size_t)j * 128 + (size_t)ch * 16);
        }
        CP_COMMIT();
    };

    // prologue: group0 = {P, Q, B0}; group1 = {B1}; group2 = {B2}
    {
        #pragma unroll
        for (int i = 0; i < 4; i++) {
            int o = i * 256 + tid;
            int row = o >> 6, ch = o & 63;
            cp16(smb + OFF_PB + (uint32_t)row * 1024 + (uint32_t)ch * 16,
                 g_Pb + ((size_t)(dblk * 16 + row) * BSZN + b) * 1024 + (size_t)ch * 16);
        }
        #pragma unroll
        for (int i = 0; i < 2; i++) {
            int o = i * 256 + tid;
            int row = o >> 6, ch = o & 63;
            cp16(smb + OFF_QB + (uint32_t)row * QSTRIDE + (uint32_t)ch * 16,
                 g_Qb + ((size_t)(hblk * 8 + row) * BSZN + b) * 1024 + (size_t)ch * 16);
        }
        issue_B(0, 0);   // commits {P,Q,B0}
        issue_B(1, 1);
        issue_B(2, 2);
    }

    // mainloop: wait (3 chunks behind) -> sync -> issue B(j+3) -> MMA(j)
    #pragma unroll 1
    for (int j = 0; j < 8; j++) {
        if (j < 6)      cp_wait<2>();    // B(j) group done; {B(j+1),B(j+2)} in flight
        else if (j == 6) cp_wait<1>();
        else             cp_wait<0>();
        __syncthreads();                 // cross-thread visibility of B(j);
                                         // all readers of stage (j-1)&3 are past MMA(j-1)
        if (j < 5) issue_B(j + 3, (j + 3) & 3);

        const uint32_t BsB = smb + OFF_B(j & 3);
        const uint32_t kchunk = (uint32_t)j * 128;
        uint32_t bb[2][8];
        ldsm_x4(&bb[0][0], BsB + bOff);
        ldsm_x4(&bb[0][4], BsB + 16 * ASTRIDE + bOff);
        #pragma unroll
        for (int ks = 0; ks < 4; ks++) {
            const int cu = ks & 1, nx = cu ^ 1;
            if (ks < 3) {
                ldsm_x4(&bb[nx][0], BsB + bOff + (ks + 1) * 32);
                ldsm_x4(&bb[nx][4], BsB + 16 * ASTRIDE + bOff + (ks + 1) * 32);
            }
            // batched operand loads: 1 q + 8 p LDS.64 (MLP=9)
            const uint32_t ko = kchunk + (uint32_t)ks * 32;
            uint2 q = lds64(qb2 + ko);
            uint2 p[4][2];
            #pragma unroll
            for (int mf = 0; mf < 4; mf++) {
                const uint32_t pb = pb2 + (uint32_t)mf * 2048 + ko;
                p[mf][0] = lds64(pb);
                p[mf][1] = lds64(pb + 1024);
            }
            #pragma unroll
            for (int mf = 0; mf < 4; mf++) {
                uint32_t a[4];
                a[0] = bf2_addrelu(p[mf][0].x, q.x);
                a[1] = bf2_addrelu(p[mf][1].x, q.x);
                a[2] = bf2_addrelu(p[mf][0].y, q.y);
                a[3] = bf2_addrelu(p[mf][1].y, q.y);
                #pragma unroll
                for (int nf = 0; nf < 4; nf++)
                    mma_bf16(c[mf][nf], a, &bb[cu][nf * 2]);
            }
        }
    }

    // single-pass epilogue: stage 128x132, per-row log-softmax
    // Ssm spans 1024..68608 — overlaps P/Q and B stages 0-2 only; chunk 7
    // read stage 3 (81152..99584), untouched until all warps pass the sync.
    float* Ssm = reinterpret_cast<float*>(dsm + 1024);
    __syncthreads();
    #pragma unroll
    for (int mf = 0; mf < 4; mf++) {
        #pragma unroll
        for (int nf = 0; nf < 4; nf++) {
            int rl = wm * 64 + mf * 16 + g;
            int col = wn * 32 + nf * 8 + 2 * tg;
            *reinterpret_cast<float2*>(&Ssm[rl * 132 + col]) =
                make_float2(c[mf][nf][0], c[mf][nf][1]);
            *reinterpret_cast<float2*>(&Ssm[(rl + 8) * 132 + col]) =
                make_float2(c[mf][nf][2], c[mf][nf][3]);
        }
    }
    __syncthreads();
    #pragma unroll
    for (int i = 0; i < 16; i++) {
        int rl = wid * 16 + i;
        float4 v = *reinterpret_cast<const float4*>(&Ssm[rl * 132 + lane * 4]);
        v.x += bps[lane * 4 + 0];
        v.y += bps[lane * 4 + 1];
        v.z += bps[lane * 4 + 2];
        v.w += bps[lane * 4 + 3];
        float mx = fmaxf(fmaxf(v.x, v.y), fmaxf(v.z, v.w));
        #pragma unroll
        for (int off = 16; off > 0; off >>= 1)
            mx = fmaxf(mx, __shfl_xor_sync(0xffffffffu, mx, off));
        mx = fmaxf(mx, 0.f);  // nil column
        float se = __expf(v.x - mx) + __expf(v.y - mx) +
                   __expf(v.z - mx) + __expf(v.w - mx);
        #pragma unroll
        for (int off = 16; off > 0; off >>= 1)
            se += __shfl_xor_sync(0xffffffffu, se, off);
        se += __expf(-mx);  // nil column contribution
        float lse = mx + __logf(se);
        int d = dblk * 16 + (rl >> 3);
        int h = hblk * 8 + (rl & 7);
        float* op = out + (size_t)((d * BSZN + b) * HEADN + h) * (RELN + 1);
        if (lane == 0) op[0] = -lse;
        op[1 + lane * 4 + 0] = v.x - lse;
        op[1 + lane * 4 + 1] = v.y - lse;
        op[1 + lane * 4 + 2] = v.z - lse;
        op[1 + lane * 4 + 3] = v.w - lse;
    }
}

// ---------------------------------------------------------------------------
extern "C" void kernel_launch(void* const* d_in, const int* in_sizes, int n_in,
                              void* d_out, int out_size) {
    const float* outs = (const float*)d_in[0];  // [96,16,512]
    const float* gs   = (const float*)d_in[1];  // [96,16,512]
    const float* Wt   = (const float*)d_in[2];  // [512,1024]
    const float* bt   = (const float*)d_in[3];  // [512]
    const float* Wp   = (const float*)d_in[4];  // [128,512]
    const float* bp   = (const float*)d_in[5];  // [128]
    float* out = (float*)d_out;                 // [96,16,96,129]

    (void)in_sizes; (void)n_in; (void)out_size;

    static bool attr_set = false;
    if (!attr_set) {
        cudaFuncSetAttribute(rel_kernel,
                             cudaFuncAttributeMaxDynamicSharedMemorySize,
                             REL_SMEM);
        cudaFuncSetAttribute(projb_kernel,
                             cudaFuncAttributeMaxDynamicSharedMemorySize,
                             PJ_SMEM);
        attr_set = true;
    }

    prep_kernel<<<R_WP / 256, 256>>>(outs, gs, Wt, Wp);        // 2112 blocks

    dim3 pg(DIMN / 128, 1536 / 128, 2);           // (4, 12, 2)
    projb_kernel<<<pg, 256, PJ_SMEM>>>(bt);

    dim3 mg(HEADN / 8, DEPN / 16, BSZN);          // (12, 6, 16)
    rel_kernel<<<mg, 256, REL_SMEM>>>(bp, out);
}